// round 12
// baseline (speedup 1.0000x reference)
#include <cuda_runtime.h>

// MaxLocaldist: per output pixel, max pairwise L2 distance among the 9 RGB
// pixels of the 3x3 neighborhood. Input (32,3,224,224) f32 NCHW.
// Output (32,1,224,224) f32, 1-pixel zero border.
//
// Column-pair decomposition + temporal d2 caching, 2 output rows/iteration
// (as R11), plus an L1 PREFETCH PIPELINE: in steady state every inner-loop
// load was an L2 hit (~240cyc) because each block reads each input row only
// once (the 9x reuse is cross-block). prefetch.global.L1 for iteration t+1's
// two rows is issued at the top of iteration t (zero register cost); one
// full iteration body (~400cyc) later the demand loads hit L1 (~32cyc).

#define HD 224
#define WD 224
#define HWD (HD * WD)
#define FULLMASK 0xffffffffu

__device__ __forceinline__ void pf_l1(const float* p) {
    asm volatile("prefetch.global.L1 [%0];" :: "l"(p));
}

__device__ __forceinline__ float d2s(const float a[3], const float b[3]) {
    const float dx = a[0] - b[0];
    const float dy = a[1] - b[1];
    const float dz = a[2] - b[2];
    return fmaf(dx, dx, fmaf(dy, dy, dz * dz));
}

__device__ __forceinline__ float max9(float e0, float e1, float e2, float e3,
                                      float e4, float e5, float e6, float e7,
                                      float e8) {
    const float m01 = fmaxf(e0, e1), m23 = fmaxf(e2, e3);
    const float m45 = fmaxf(e4, e5), m67 = fmaxf(e6, e7);
    return fmaxf(fmaxf(fmaxf(m01, m23), fmaxf(m45, m67)), e8);
}

__global__ __launch_bounds__(256, 4) void maxlocaldist_kernel(
    const float* __restrict__ x, float* __restrict__ out)
{
    const int lane = threadIdx.x & 31;
    const int wgrp = threadIdx.x >> 5;          // 0..7: 30 output cols per warp
    const int b    = blockIdx.z;
    const int h0   = blockIdx.y * 8;            // 8 output rows per block
    const int c0   = wgrp * 30 + lane;

    const float* xb = x + (long)b * 3 * HWD;

    int col[3];
#pragma unroll
    for (int j = 0; j < 3; j++) col[j] = min(c0 + j, WD - 1);

    // 4-slot rolling window: pt[slot][colj][ch]; slot = relative-row & 3
    float pt[4][3][3];
    float D01[4][4], D02[4][4], sd1[4], sd2[4];

    // ---- prologue: rows h0-1 (slot 0, clamped) and h0 (slot 1)
#pragma unroll
    for (int s = 0; s < 2; s++) {
        const int r = max(h0 - 1 + s, 0);
#pragma unroll
        for (int ch = 0; ch < 3; ch++)
#pragma unroll
            for (int j = 0; j < 3; j++)
                pt[s][j][ch] = __ldg(xb + ch * HWD + r * WD + col[j]);
    }
    // prefetch iteration 0's demand rows (h0+1, h0+2)
    {
        const int r1 = h0 + 1;
        const int r2 = min(h0 + 2, HD - 1);
#pragma unroll
        for (int ch = 0; ch < 3; ch++) {
            pf_l1(xb + ch * HWD + r1 * WD + col[0]);
            pf_l1(xb + ch * HWD + r1 * WD + col[2]);
            pf_l1(xb + ch * HWD + r2 * WD + col[0]);
            pf_l1(xb + ch * HWD + r2 * WD + col[2]);
        }
    }

    D01[0][0] = d2s(pt[0][0], pt[0][1]);
    D01[0][1] = d2s(pt[0][0], pt[1][1]);
    D01[1][0] = d2s(pt[1][0], pt[0][1]);
    D01[1][1] = d2s(pt[1][0], pt[1][1]);
    D02[0][0] = d2s(pt[0][0], pt[0][2]);
    D02[0][1] = d2s(pt[0][0], pt[1][2]);
    D02[1][0] = d2s(pt[1][0], pt[0][2]);
    D02[1][1] = d2s(pt[1][0], pt[1][2]);
    sd1[0]    = d2s(pt[0][0], pt[1][0]);

    const int  w_out   = c0 + 1;
    const bool wvalid  = (lane < 30) && (w_out <= WD - 1);
    const bool zerocol = (wgrp == 0) && (lane == 31);

#pragma unroll
    for (int t = 0; t < 4; t++) {
        const int ha = h0 + 2 * t;
        const int hb = ha + 1;
        const int sA = (2 * t)     & 3;     // row ha-1
        const int sB = (2 * t + 1) & 3;     // row ha
        const int sC = (2 * t + 2) & 3;     // row hb
        const int sD = (2 * t + 3) & 3;     // row hb+1

        // ---- issue BOTH demand-row loads back-to-back (L1 hits via prefetch)
#pragma unroll
        for (int ch = 0; ch < 3; ch++)
#pragma unroll
            for (int j = 0; j < 3; j++)
                pt[sC][j][ch] = __ldg(xb + ch * HWD + hb * WD + col[j]);

        const int rD = min(ha + 2, HD - 1);
#pragma unroll
        for (int ch = 0; ch < 3; ch++)
#pragma unroll
            for (int j = 0; j < 3; j++)
                pt[sD][j][ch] = __ldg(xb + ch * HWD + rD * WD + col[j]);

        // ---- prefetch iteration t+1's rows (ha+3, ha+4) into L1
        if (t < 3) {
            const int r1 = min(ha + 3, HD - 1);
            const int r2 = min(ha + 4, HD - 1);
#pragma unroll
            for (int ch = 0; ch < 3; ch++) {
                pf_l1(xb + ch * HWD + r1 * WD + col[0]);
                pf_l1(xb + ch * HWD + r1 * WD + col[2]);
                pf_l1(xb + ch * HWD + r2 * WD + col[0]);
                pf_l1(xb + ch * HWD + r2 * WD + col[2]);
            }
        }

        // ---- refresh entries involving row C
        D01[sC][sA] = d2s(pt[sC][0], pt[sA][1]);
        D01[sC][sB] = d2s(pt[sC][0], pt[sB][1]);
        D01[sC][sC] = d2s(pt[sC][0], pt[sC][1]);
        D01[sA][sC] = d2s(pt[sA][0], pt[sC][1]);
        D01[sB][sC] = d2s(pt[sB][0], pt[sC][1]);
        D02[sC][sA] = d2s(pt[sC][0], pt[sA][2]);
        D02[sC][sB] = d2s(pt[sC][0], pt[sB][2]);
        D02[sC][sC] = d2s(pt[sC][0], pt[sC][2]);
        D02[sA][sC] = d2s(pt[sA][0], pt[sC][2]);
        D02[sB][sC] = d2s(pt[sB][0], pt[sC][2]);
        sd2[sA]     = d2s(pt[sA][0], pt[sC][0]);
        sd1[sB]     = d2s(pt[sB][0], pt[sC][0]);

        // ---- output ha (rows sA,sB,sC) — independent of row D's refresh
        const float Sa = fmaxf(fmaxf(sd1[sA], sd2[sA]), sd1[sB]);
        const float P01a = max9(D01[sA][sA], D01[sA][sB], D01[sB][sA],
                                D01[sB][sB], D01[sC][sA], D01[sC][sB],
                                D01[sC][sC], D01[sA][sC], D01[sB][sC]);
        const float P02a = max9(D02[sA][sA], D02[sA][sB], D02[sB][sA],
                                D02[sB][sB], D02[sC][sA], D02[sC][sB],
                                D02[sC][sC], D02[sA][sC], D02[sB][sC]);

        const float S1a = __shfl_down_sync(FULLMASK, Sa,   1);
        const float S2a = __shfl_down_sync(FULLMASK, Sa,   2);
        const float Qa  = __shfl_down_sync(FULLMASK, P01a, 1);
        const float ma  = fmaxf(fmaxf(fmaxf(Sa, S1a), fmaxf(S2a, P01a)),
                                fmaxf(Qa, P02a));
        float va;
        asm("sqrt.approx.f32 %0, %1;" : "=f"(va) : "f"(ma));
        {
            const bool border = (ha == 0) || (w_out == WD - 1);
            if (wvalid)
                out[((long)b * HD + ha) * WD + w_out] = border ? 0.0f : va;
            if (zerocol)
                out[((long)b * HD + ha) * WD] = 0.0f;
        }

        // ---- refresh entries involving row D
        D01[sD][sB] = d2s(pt[sD][0], pt[sB][1]);
        D01[sD][sC] = d2s(pt[sD][0], pt[sC][1]);
        D01[sD][sD] = d2s(pt[sD][0], pt[sD][1]);
        D01[sB][sD] = d2s(pt[sB][0], pt[sD][1]);
        D01[sC][sD] = d2s(pt[sC][0], pt[sD][1]);
        D02[sD][sB] = d2s(pt[sD][0], pt[sB][2]);
        D02[sD][sC] = d2s(pt[sD][0], pt[sC][2]);
        D02[sD][sD] = d2s(pt[sD][0], pt[sD][2]);
        D02[sB][sD] = d2s(pt[sB][0], pt[sD][2]);
        D02[sC][sD] = d2s(pt[sC][0], pt[sD][2]);
        sd2[sB]     = d2s(pt[sB][0], pt[sD][0]);
        sd1[sC]     = d2s(pt[sC][0], pt[sD][0]);

        // ---- output hb (rows sB,sC,sD)
        const float Sb = fmaxf(fmaxf(sd1[sB], sd2[sB]), sd1[sC]);
        const float P01b = max9(D01[sB][sB], D01[sB][sC], D01[sC][sB],
                                D01[sC][sC], D01[sD][sB], D01[sD][sC],
                                D01[sD][sD], D01[sB][sD], D01[sC][sD]);
        const float P02b = max9(D02[sB][sB], D02[sB][sC], D02[sC][sB],
                                D02[sC][sC], D02[sD][sB], D02[sD][sC],
                                D02[sD][sD], D02[sB][sD], D02[sC][sD]);

        const float S1b = __shfl_down_sync(FULLMASK, Sb,   1);
        const float S2b = __shfl_down_sync(FULLMASK, Sb,   2);
        const float Qb  = __shfl_down_sync(FULLMASK, P01b, 1);
        const float mb  = fmaxf(fmaxf(fmaxf(Sb, S1b), fmaxf(S2b, P01b)),
                                fmaxf(Qb, P02b));
        float vb;
        asm("sqrt.approx.f32 %0, %1;" : "=f"(vb) : "f"(mb));
        {
            const bool border = (hb == HD - 1) || (w_out == WD - 1);
            if (wvalid)
                out[((long)b * HD + hb) * WD + w_out] = border ? 0.0f : vb;
            if (zerocol)
                out[((long)b * HD + hb) * WD] = 0.0f;
        }
    }
}

extern "C" void kernel_launch(void* const* d_in, const int* in_sizes, int n_in,
                              void* d_out, int out_size)
{
    const float* x = (const float*)d_in[0];
    float* out = (float*)d_out;

    dim3 block(256, 1, 1);
    dim3 grid(1, HD / 8, 32);   // 28 row-tiles x 32 batches = 896 blocks
    maxlocaldist_kernel<<<grid, block>>>(x, out);
}

// round 13
// speedup vs baseline: 1.0039x; 1.0039x over previous
#include <cuda_runtime.h>

// MaxLocaldist: per output pixel, max pairwise L2 distance among the 9 RGB
// pixels of the 3x3 neighborhood. Input (32,3,224,224) f32 NCHW.
// Output (32,1,224,224) f32, 1-pixel zero border.
//
// Column-pair decomposition (12 evals/output, shfl-shared) with CARRIED
// RUNNING MAXES instead of full d2 matrices:
//   P01 = max(W01, 5 fresh evals involving the new row)
//   W01' = max(e_BX, e_XB, e_XX, nn01);  nn01' = e_XX   (exact recurrence)
// Persistent state drops 48 -> 32 floats -> regs <=51 -> 5 blocks/SM
// (~60% occupancy). Prior rounds proved the 12-eval dataflow is issue-
// starved at 40% occ (issue 45-68%); R1 showed 78% issue at 63% occ.

#define HD 224
#define WD 224
#define HWD (HD * WD)
#define R_ROWS 8
#define FULLMASK 0xffffffffu

__device__ __forceinline__ float d2s(const float a[3], const float b[3]) {
    const float dx = a[0] - b[0];
    const float dy = a[1] - b[1];
    const float dz = a[2] - b[2];
    return fmaf(dx, dx, fmaf(dy, dy, dz * dz));
}

__global__ __launch_bounds__(256, 5) void maxlocaldist_kernel(
    const float* __restrict__ x, float* __restrict__ out)
{
    const int lane = threadIdx.x & 31;
    const int wgrp = threadIdx.x >> 5;          // 0..7: 30 output cols per warp
    const int b    = blockIdx.z;
    const int h0   = blockIdx.y * R_ROWS;
    const int c0   = wgrp * 30 + lane;

    const float* xb = x + (long)b * 3 * HWD;

    int col[3];
#pragma unroll
    for (int j = 0; j < 3; j++) col[j] = min(c0 + j, WD - 1);

    // rolling 3-row window: pt[slot][colj][ch]
    float pt[3][3][3];

    // prologue: rows h0-1 (slot 0, clamped) and h0 (slot 1)
#pragma unroll
    for (int s = 0; s < 2; s++) {
        const int r = max(h0 - 1 + s, 0);
#pragma unroll
        for (int ch = 0; ch < 3; ch++)
#pragma unroll
            for (int j = 0; j < 3; j++)
                pt[s][j][ch] = __ldg(xb + ch * HWD + r * WD + col[j]);
    }

    // carried running maxes:
    //  W01 = max d2 over col0xcol1 pairs within the two surviving rows
    //  nn01 = the (new,new) entry of the last-added row; likewise for 02
    //  sdc  = within-col0 d2 of the two surviving rows
    float W01, nn01, W02, nn02, sdc;
    {
        const float e00 = d2s(pt[0][0], pt[0][1]);
        const float e01 = d2s(pt[0][0], pt[1][1]);
        const float e10 = d2s(pt[1][0], pt[0][1]);
        const float e11 = d2s(pt[1][0], pt[1][1]);
        W01  = fmaxf(fmaxf(e00, e01), fmaxf(e10, e11));
        nn01 = e11;
        const float f00 = d2s(pt[0][0], pt[0][2]);
        const float f01 = d2s(pt[0][0], pt[1][2]);
        const float f10 = d2s(pt[1][0], pt[0][2]);
        const float f11 = d2s(pt[1][0], pt[1][2]);
        W02  = fmaxf(fmaxf(f00, f01), fmaxf(f10, f11));
        nn02 = f11;
        sdc  = d2s(pt[0][0], pt[1][0]);
    }

    const int  w_out   = c0 + 1;
    const bool wvalid  = (lane < 30) && (w_out <= WD - 1);
    const bool zerocol = (wgrp == 0) && (lane == 31);

#pragma unroll
    for (int rr = 0; rr < R_ROWS; rr++) {
        const int h  = h0 + rr;
        const int sA = rr % 3;          // row h-1
        const int sB = (rr + 1) % 3;    // row h
        const int sX = (rr + 2) % 3;    // row h+1 (loaded now)

        const int rn = min(h + 1, HD - 1);
#pragma unroll
        for (int ch = 0; ch < 3; ch++)
#pragma unroll
            for (int j = 0; j < 3; j++)
                pt[sX][j][ch] = __ldg(xb + ch * HWD + rn * WD + col[j]);

        // 12 fresh evals involving the new row
        const float e01_XA = d2s(pt[sX][0], pt[sA][1]);
        const float e01_XB = d2s(pt[sX][0], pt[sB][1]);
        const float e01_XX = d2s(pt[sX][0], pt[sX][1]);
        const float e01_AX = d2s(pt[sA][0], pt[sX][1]);
        const float e01_BX = d2s(pt[sB][0], pt[sX][1]);

        const float e02_XA = d2s(pt[sX][0], pt[sA][2]);
        const float e02_XB = d2s(pt[sX][0], pt[sB][2]);
        const float e02_XX = d2s(pt[sX][0], pt[sX][2]);
        const float e02_AX = d2s(pt[sA][0], pt[sX][2]);
        const float e02_BX = d2s(pt[sB][0], pt[sX][2]);

        const float sd_f1  = d2s(pt[sX][0], pt[sA][0]);
        const float sd_f2  = d2s(pt[sX][0], pt[sB][0]);

        // column stats for output h
        const float S   = fmaxf(fmaxf(sd_f1, sd_f2), sdc);
        const float P01 = fmaxf(fmaxf(fmaxf(e01_XA, e01_XB),
                                      fmaxf(e01_XX, e01_AX)),
                                fmaxf(e01_BX, W01));
        const float P02 = fmaxf(fmaxf(fmaxf(e02_XA, e02_XB),
                                      fmaxf(e02_XX, e02_AX)),
                                fmaxf(e02_BX, W02));

        // update carries for the next window {B, X}
        W01 = fmaxf(fmaxf(e01_BX, e01_XB), fmaxf(e01_XX, nn01));
        nn01 = e01_XX;
        W02 = fmaxf(fmaxf(e02_BX, e02_XB), fmaxf(e02_XX, nn02));
        nn02 = e02_XX;
        sdc = sd_f2;

        const float S1 = __shfl_down_sync(FULLMASK, S,   1);
        const float S2 = __shfl_down_sync(FULLMASK, S,   2);
        const float Q  = __shfl_down_sync(FULLMASK, P01, 1);

        const float m = fmaxf(fmaxf(fmaxf(S, S1), fmaxf(S2, P01)),
                              fmaxf(Q, P02));
        float v;
        asm("sqrt.approx.f32 %0, %1;" : "=f"(v) : "f"(m));

        const bool border = (h == 0) || (h == HD - 1) || (w_out == WD - 1);
        if (wvalid)
            out[((long)b * HD + h) * WD + w_out] = border ? 0.0f : v;
        if (zerocol)
            out[((long)b * HD + h) * WD] = 0.0f;
    }
}

extern "C" void kernel_launch(void* const* d_in, const int* in_sizes, int n_in,
                              void* d_out, int out_size)
{
    const float* x = (const float*)d_in[0];
    float* out = (float*)d_out;

    dim3 block(256, 1, 1);
    dim3 grid(1, HD / R_ROWS, 32);   // 28 x 32 = 896 blocks
    maxlocaldist_kernel<<<grid, block>>>(x, out);
}

// round 14
// speedup vs baseline: 1.0078x; 1.0039x over previous
#include <cuda_runtime.h>

// MaxLocaldist: per output pixel, max pairwise L2 distance among the 9 RGB
// pixels of the 3x3 neighborhood. Input (32,3,224,224) f32 NCHW.
// Output (32,1,224,224) f32, 1-pixel zero border.
//
// Column-pair decomposition (12 evals/output, shfl-shared) with CARRIED
// RUNNING MAXES instead of full d2 matrices:
//   P01 = max(W01, 5 fresh evals involving the new row)
//   W01' = max(e_BX, e_XB, e_XX, nn01);  nn01' = e_XX   (exact recurrence)
// Persistent state drops 48 -> 32 floats -> regs <=51 -> 5 blocks/SM
// (~60% occupancy). Prior rounds proved the 12-eval dataflow is issue-
// starved at 40% occ (issue 45-68%); R1 showed 78% issue at 63% occ.

#define HD 224
#define WD 224
#define HWD (HD * WD)
#define R_ROWS 8
#define FULLMASK 0xffffffffu

__device__ __forceinline__ float d2s(const float a[3], const float b[3]) {
    const float dx = a[0] - b[0];
    const float dy = a[1] - b[1];
    const float dz = a[2] - b[2];
    return fmaf(dx, dx, fmaf(dy, dy, dz * dz));
}

__global__ __launch_bounds__(256, 5) void maxlocaldist_kernel(
    const float* __restrict__ x, float* __restrict__ out)
{
    const int lane = threadIdx.x & 31;
    const int wgrp = threadIdx.x >> 5;          // 0..7: 30 output cols per warp
    const int b    = blockIdx.z;
    const int h0   = blockIdx.y * R_ROWS;
    const int c0   = wgrp * 30 + lane;

    const float* xb = x + (long)b * 3 * HWD;

    int col[3];
#pragma unroll
    for (int j = 0; j < 3; j++) col[j] = min(c0 + j, WD - 1);

    // rolling 3-row window: pt[slot][colj][ch]
    float pt[3][3][3];

    // prologue: rows h0-1 (slot 0, clamped) and h0 (slot 1)
#pragma unroll
    for (int s = 0; s < 2; s++) {
        const int r = max(h0 - 1 + s, 0);
#pragma unroll
        for (int ch = 0; ch < 3; ch++)
#pragma unroll
            for (int j = 0; j < 3; j++)
                pt[s][j][ch] = __ldg(xb + ch * HWD + r * WD + col[j]);
    }

    // carried running maxes:
    //  W01 = max d2 over col0xcol1 pairs within the two surviving rows
    //  nn01 = the (new,new) entry of the last-added row; likewise for 02
    //  sdc  = within-col0 d2 of the two surviving rows
    float W01, nn01, W02, nn02, sdc;
    {
        const float e00 = d2s(pt[0][0], pt[0][1]);
        const float e01 = d2s(pt[0][0], pt[1][1]);
        const float e10 = d2s(pt[1][0], pt[0][1]);
        const float e11 = d2s(pt[1][0], pt[1][1]);
        W01  = fmaxf(fmaxf(e00, e01), fmaxf(e10, e11));
        nn01 = e11;
        const float f00 = d2s(pt[0][0], pt[0][2]);
        const float f01 = d2s(pt[0][0], pt[1][2]);
        const float f10 = d2s(pt[1][0], pt[0][2]);
        const float f11 = d2s(pt[1][0], pt[1][2]);
        W02  = fmaxf(fmaxf(f00, f01), fmaxf(f10, f11));
        nn02 = f11;
        sdc  = d2s(pt[0][0], pt[1][0]);
    }

    const int  w_out   = c0 + 1;
    const bool wvalid  = (lane < 30) && (w_out <= WD - 1);
    const bool zerocol = (wgrp == 0) && (lane == 31);

#pragma unroll
    for (int rr = 0; rr < R_ROWS; rr++) {
        const int h  = h0 + rr;
        const int sA = rr % 3;          // row h-1
        const int sB = (rr + 1) % 3;    // row h
        const int sX = (rr + 2) % 3;    // row h+1 (loaded now)

        const int rn = min(h + 1, HD - 1);
#pragma unroll
        for (int ch = 0; ch < 3; ch++)
#pragma unroll
            for (int j = 0; j < 3; j++)
                pt[sX][j][ch] = __ldg(xb + ch * HWD + rn * WD + col[j]);

        // 12 fresh evals involving the new row
        const float e01_XA = d2s(pt[sX][0], pt[sA][1]);
        const float e01_XB = d2s(pt[sX][0], pt[sB][1]);
        const float e01_XX = d2s(pt[sX][0], pt[sX][1]);
        const float e01_AX = d2s(pt[sA][0], pt[sX][1]);
        const float e01_BX = d2s(pt[sB][0], pt[sX][1]);

        const float e02_XA = d2s(pt[sX][0], pt[sA][2]);
        const float e02_XB = d2s(pt[sX][0], pt[sB][2]);
        const float e02_XX = d2s(pt[sX][0], pt[sX][2]);
        const float e02_AX = d2s(pt[sA][0], pt[sX][2]);
        const float e02_BX = d2s(pt[sB][0], pt[sX][2]);

        const float sd_f1  = d2s(pt[sX][0], pt[sA][0]);
        const float sd_f2  = d2s(pt[sX][0], pt[sB][0]);

        // column stats for output h
        const float S   = fmaxf(fmaxf(sd_f1, sd_f2), sdc);
        const float P01 = fmaxf(fmaxf(fmaxf(e01_XA, e01_XB),
                                      fmaxf(e01_XX, e01_AX)),
                                fmaxf(e01_BX, W01));
        const float P02 = fmaxf(fmaxf(fmaxf(e02_XA, e02_XB),
                                      fmaxf(e02_XX, e02_AX)),
                                fmaxf(e02_BX, W02));

        // update carries for the next window {B, X}
        W01 = fmaxf(fmaxf(e01_BX, e01_XB), fmaxf(e01_XX, nn01));
        nn01 = e01_XX;
        W02 = fmaxf(fmaxf(e02_BX, e02_XB), fmaxf(e02_XX, nn02));
        nn02 = e02_XX;
        sdc = sd_f2;

        const float S1 = __shfl_down_sync(FULLMASK, S,   1);
        const float S2 = __shfl_down_sync(FULLMASK, S,   2);
        const float Q  = __shfl_down_sync(FULLMASK, P01, 1);

        const float m = fmaxf(fmaxf(fmaxf(S, S1), fmaxf(S2, P01)),
                              fmaxf(Q, P02));
        float v;
        asm("sqrt.approx.f32 %0, %1;" : "=f"(v) : "f"(m));

        const bool border = (h == 0) || (h == HD - 1) || (w_out == WD - 1);
        if (wvalid)
            out[((long)b * HD + h) * WD + w_out] = border ? 0.0f : v;
        if (zerocol)
            out[((long)b * HD + h) * WD] = 0.0f;
    }
}

extern "C" void kernel_launch(void* const* d_in, const int* in_sizes, int n_in,
                              void* d_out, int out_size)
{
    const float* x = (const float*)d_in[0];
    float* out = (float*)d_out;

    dim3 block(256, 1, 1);
    dim3 grid(1, HD / R_ROWS, 32);   // 28 x 32 = 896 blocks
    maxlocaldist_kernel<<<grid, block>>>(x, out);
}